// round 5
// baseline (speedup 1.0000x reference)
#include <cuda_runtime.h>
#include <cstdint>

// CostVolume: cost[b,i,h,x] = (1/128) sum_c L[b,c,h,x]*R[b,c,h,x-i], 0 for x<i.
// b=8 c=128 h=96 w=320, 48 disparities, fp32.
// FFMA2 kernel, conflict-free XOR-swizzled smem, cp.async double buffering.
// CTA = 1 unit (b,h,x-tile of 128) = 2 warps. Thread: 16 x (8 pairs) x 6 i.

typedef unsigned long long ull;

#define BB 8
#define CH 128
#define HH 96
#define WW 320
#define MAXD 48
#define PLANE (HH*WW)

#define CC 8                          // channels per chunk
#define NCHUNK (CH/CC)                // 16
#define LROWB 512                     // L row bytes (128 floats)
#define RROWB 1024                    // R row bytes (176 used, padded for clean swizzle)
#define LAREA (CC*LROWB)              // 4096
#define STAGE_BYTES (LAREA + CC*RROWB)     // 12288
#define SMEM_TOTAL (2*STAGE_BYTES)         // 24576

// swizzle: fold bits 7,8 into bits 4,5 (keeps 16B blocks intact)
#define SWZ(o) ((o) ^ (((o) >> 3) & 0x30))

__device__ __forceinline__ void cp16(uint32_t dst, const void* src, uint32_t sz){
    asm volatile("cp.async.ca.shared.global [%0], [%1], 16, %2;"
                 :: "r"(dst), "l"(src), "r"(sz) : "memory");
}
__device__ __forceinline__ uint32_t smem_u32(const void* p){
    uint32_t a;
    asm("{ .reg .u64 t; cvta.to.shared.u64 t, %1; cvt.u32.u64 %0, t; }" : "=r"(a) : "l"(p));
    return a;
}
__device__ __forceinline__ ull pack2(float lo, float hi){
    ull d; asm("mov.b64 %0, {%1,%2};" : "=l"(d) : "f"(lo), "f"(hi)); return d;
}
__device__ __forceinline__ void fma2(ull& a, ull x, ull y){
    asm("fma.rn.f32x2 %0, %1, %2, %0;" : "+l"(a) : "l"(x), "l"(y));
}
__device__ __forceinline__ ull mul2(ull x, ull y){
    ull d; asm("mul.rn.f32x2 %0, %1, %2;" : "=l"(d) : "l"(x), "l"(y)); return d;
}

__global__ __launch_bounds__(64, 5)
void costvol_v5_kernel(const float* __restrict__ L,
                       const float* __restrict__ R,
                       float* __restrict__ out)
{
    extern __shared__ char smem[];
    const uint32_t sbase = smem_u32(smem);

    const int tid  = threadIdx.x;       // 0..63
    const int w01  = tid >> 5;
    const int lane = tid & 31;
    const int xq = lane >> 2;           // 0..7
    const int ig = lane & 3;            // 0..3

    const int unit = blockIdx.x;
    const int xt = unit % 3;
    const int bh = unit / 3;
    const int h  = bh % HH;
    const int b  = bh / HH;
    const int x0 = xt * 96;             // tiles {0,96,192} width 128; overlap rows
                                        // recompute bitwise-identical values

    const float* Lbh = L + ((size_t)b * CH * HH + h) * WW;
    const float* Rbh = R + ((size_t)b * CH * HH + h) * WW;

    const int X  = x0 + 16 * xq;
    const int i0 = 24 * w01 + 6 * ig;
    const int base = 48 + 16 * xq - i0;   // even, base-6 >= 0

    // precomputed swizzled intra-row byte offsets
    uint32_t LoffSw[4], RoffSw[11];
    #pragma unroll
    for (int t = 0; t < 4; t++){
        uint32_t o = (uint32_t)(64 * xq + 16 * t);
        LoffSw[t] = SWZ(o);
    }
    {
        uint32_t E = (uint32_t)(4 * (base - 6));
        #pragma unroll
        for (int j = 0; j < 11; j++){
            uint32_t o = E + 8u * j;
            RoffSw[j] = SWZ(o);
        }
    }

    ull acc[6][8];
    #pragma unroll
    for (int a = 0; a < 6; a++)
        #pragma unroll
        for (int u = 0; u < 8; u++) acc[a][u] = 0ULL;

    // ---- cooperative async load of one chunk ----
    // L: 8cc x 32 lines (512B rows). R: 8cc x 44 lines (1024B rows, 704B used).
    auto issue = [&](int k){
        const int c0 = k * CC;
        const uint32_t sb = sbase + (uint32_t)(k & 1) * STAGE_BYTES;
        #pragma unroll
        for (int it = 0; it < 10; it++){
            int idx = tid + it * 64;
            if (idx < 608){
                int cc = idx / 76;
                int j  = idx - cc * 76;
                const float* gp;
                uint32_t dst, sz = 16;
                if (j < 32){
                    gp  = Lbh + (size_t)(c0 + cc) * PLANE + x0 + 4 * j;
                    dst = sb + (uint32_t)cc * LROWB + SWZ((uint32_t)(16 * j));
                } else {
                    int jr = j - 32;
                    int xr = x0 - 48 + 4 * jr;
                    int xs = xr < 0 ? 0 : xr;
                    gp  = Rbh + (size_t)(c0 + cc) * PLANE + xs;
                    sz  = (xr >= 0) ? 16u : 0u;      // zero-fill x' < 0
                    dst = sb + LAREA + (uint32_t)cc * RROWB + SWZ((uint32_t)(16 * jr));
                }
                cp16(dst, gp, sz);
            }
        }
    };

    // ---- compute one chunk ----
    auto compute = [&](int k){
        const char* st = smem + (uint32_t)(k & 1) * STAGE_BYTES;
        #pragma unroll
        for (int cc = 0; cc < CC; cc++){
            const char* Lr = st + cc * LROWB;
            const char* Rr = st + LAREA + cc * RROWB;

            ull l2[8];
            #pragma unroll
            for (int t = 0; t < 4; t++){
                ulonglong2 v = *(const ulonglong2*)(Lr + LoffSw[t]);
                l2[2*t]   = v.x;
                l2[2*t+1] = v.y;
            }
            ull q[11];
            #pragma unroll
            for (int j = 0; j < 11; j++)
                q[j] = *(const ull*)(Rr + RoffSw[j]);

            // even disparities a=2a2: aligned pairs, no packing
            #pragma unroll
            for (int a2 = 0; a2 < 3; a2++)
                #pragma unroll
                for (int u = 0; u < 8; u++)
                    fma2(acc[2*a2][u], l2[u], q[u + 3 - a2]);

            // odd disparities: shifted pairs via 64-bit reg-pair moves
            ull m[10];
            #pragma unroll
            for (int jm = 0; jm < 10; jm++)
                m[jm] = (q[jm] >> 32) | (q[jm+1] << 32);

            #pragma unroll
            for (int ao = 0; ao < 3; ao++)
                #pragma unroll
                for (int u = 0; u < 8; u++)
                    fma2(acc[2*ao+1][u], l2[u], m[u + 2 - ao]);
        }
    };

    // ---- pipelined main loop ----
    issue(0);
    asm volatile("cp.async.commit_group;" ::: "memory");
    #pragma unroll 1
    for (int k = 0; k < NCHUNK; k++){
        if (k + 1 < NCHUNK){
            issue(k + 1);
            asm volatile("cp.async.commit_group;" ::: "memory");
            asm volatile("cp.async.wait_group 1;" ::: "memory");
        } else {
            asm volatile("cp.async.wait_group 0;" ::: "memory");
        }
        __syncthreads();
        compute(k);
        __syncthreads();
    }

    // ---- epilogue: scale 1/128, 16B coalesced stores ----
    const ull s2 = pack2(1.0f/128.0f, 1.0f/128.0f);
    #pragma unroll
    for (int a = 0; a < 6; a++){
        const int i = i0 + a;
        float* dst = out + (((size_t)b * MAXD + i) * HH + h) * WW + X;
        #pragma unroll
        for (int t = 0; t < 4; t++){
            ulonglong2 v;
            v.x = mul2(acc[a][2*t],     s2);
            v.y = mul2(acc[a][2*t + 1], s2);
            *(ulonglong2*)(dst + 4 * t) = v;
        }
    }
}

extern "C" void kernel_launch(void* const* d_in, const int* in_sizes, int n_in,
                              void* d_out, int out_size)
{
    const float* L = (const float*)d_in[0];
    const float* R = (const float*)d_in[1];
    float* out = (float*)d_out;

    cudaFuncSetAttribute(costvol_v5_kernel,
                         cudaFuncAttributeMaxDynamicSharedMemorySize, SMEM_TOTAL);
    dim3 grid(BB * HH * 3);   // 2304 CTAs
    costvol_v5_kernel<<<grid, 64, SMEM_TOTAL>>>(L, R, out);
}

// round 6
// speedup vs baseline: 1.6438x; 1.6438x over previous
#include <cuda_runtime.h>
#include <cuda_bf16.h>
#include <cstdint>

// CostVolume: cost[b,i,h,x] = (1/128) sum_c L[b,c,h,x]*R[b,c,h,x-i], 0 for x<i.
// b=8 c=128 h=96 w=320, 48 disp, fp32.
// Banded GEMM on legacy tensor cores (mma.sync.m16n8k16.bf16, sm_80 PTX).
// fp32 via exact bf16 hi/lo split, 3 passes: AhBh + AlBh + AhBl.
// CTA = (b, h, x-tile of 64): M=64 (x), N=112 (window x0-48..x0+63), K=128 (c).
// Warp (8/CTA) = (m-tile 16) x (half of its 64-wide n-window).

#define BB 8
#define CH 128
#define HH 96
#define WW 320
#define MAXD 48
#define PLANE (HH*WW)

#define MT 64            // CTA m (x) tile
#define NT 112           // CTA n rows
#define ROWB 256         // smem row bytes: 128 k * 2B
// smem regions
#define AHI 0
#define ALO 16384
#define BHI 32768
#define BLO 61440        // 32768 + 112*256
#define SMEM_TOTAL 90112 // 61440 + 28672

__device__ __forceinline__ uint32_t smem_u32(const void* p){
    uint32_t a;
    asm("{ .reg .u64 t; cvta.to.shared.u64 t, %1; cvt.u32.u64 %0, t; }" : "=r"(a) : "l"(p));
    return a;
}
// hi = bf16-truncate pair via PRMT, lo = rn(v - hi) pair
__device__ __forceinline__ void cvt_hilo(float v0, float v1, uint32_t& hi, uint32_t& lo){
    uint32_t u0 = __float_as_uint(v0), u1 = __float_as_uint(v1);
    uint32_t h; asm("prmt.b32 %0, %1, %2, 0x7632;" : "=r"(h) : "r"(u0), "r"(u1));
    float h0 = __uint_as_float(u0 & 0xFFFF0000u);
    float h1 = __uint_as_float(u1 & 0xFFFF0000u);
    float l0 = v0 - h0, l1 = v1 - h1;
    uint32_t l; asm("cvt.rn.bf16x2.f32 %0, %1, %2;" : "=r"(l) : "f"(l1), "f"(l0)); // hi<-l1, lo<-l0
    hi = h; lo = l;
}
__device__ __forceinline__ void ldsm_x4(uint32_t* r, uint32_t addr){
    asm volatile("ldmatrix.sync.aligned.m8n8.x4.shared.b16 {%0,%1,%2,%3}, [%4];"
                 : "=r"(r[0]), "=r"(r[1]), "=r"(r[2]), "=r"(r[3]) : "r"(addr));
}
__device__ __forceinline__ void ldsm_x2(uint32_t* r, uint32_t addr){
    asm volatile("ldmatrix.sync.aligned.m8n8.x2.shared.b16 {%0,%1}, [%2];"
                 : "=r"(r[0]), "=r"(r[1]) : "r"(addr));
}
__device__ __forceinline__ void mma16816(float* c, const uint32_t* a, const uint32_t* b){
    asm volatile("mma.sync.aligned.m16n8k16.row.col.f32.bf16.bf16.f32 "
                 "{%0,%1,%2,%3}, {%4,%5,%6,%7}, {%8,%9}, {%0,%1,%2,%3};"
                 : "+f"(c[0]), "+f"(c[1]), "+f"(c[2]), "+f"(c[3])
                 : "r"(a[0]), "r"(a[1]), "r"(a[2]), "r"(a[3]), "r"(b[0]), "r"(b[1]));
}

__global__ __launch_bounds__(256, 2)
void costvol_mma_kernel(const float* __restrict__ L,
                        const float* __restrict__ R,
                        float* __restrict__ out)
{
    extern __shared__ char smem[];
    const uint32_t sb = smem_u32(smem);

    const int tid  = threadIdx.x;
    const int warp = tid >> 5;
    const int lane = tid & 31;

    const int xt = blockIdx.x % 5;
    const int bh = blockIdx.x / 5;
    const int h  = bh % HH;
    const int b  = bh / HH;
    const int X0 = 64 * xt;

    const float* Lbh = L + ((size_t)b * CH * HH + h) * WW;
    const float* Rbh = R + ((size_t)b * CH * HH + h) * WW;

    // ---- convert A: rows m(0..63) x 64 k-pairs.  A[m][k] = L[k][X0+m] ----
    // task -> kp = task/64, m = task&63 : lanes have consecutive m -> coalesced LDG.
    #pragma unroll 4
    for (int it = 0; it < 16; it++){
        int task = tid + it * 256;
        int kp = task >> 6, m = task & 63;
        float v0 = Lbh[(size_t)(2*kp)   * PLANE + X0 + m];
        float v1 = Lbh[(size_t)(2*kp+1) * PLANE + X0 + m];
        uint32_t hi, lo; cvt_hilo(v0, v1, hi, lo);
        uint32_t c16 = (uint32_t)kp >> 2;
        uint32_t off = (uint32_t)m * ROWB + ((c16 ^ ((uint32_t)m & 15)) << 4) + (((uint32_t)kp & 3) << 2);
        *(uint32_t*)(smem + AHI + off) = hi;
        *(uint32_t*)(smem + ALO + off) = lo;
    }
    // ---- convert B: rows n(0..111) x 64 k-pairs. B[n][k] = R[k][X0-48+n] ----
    #pragma unroll 4
    for (int it = 0; it < 28; it++){
        int task = tid + it * 256;
        int n = task % NT, kp = task / NT;
        int xr = X0 - 48 + n;
        float v0 = 0.f, v1 = 0.f;
        if (xr >= 0){
            v0 = Rbh[(size_t)(2*kp)   * PLANE + xr];
            v1 = Rbh[(size_t)(2*kp+1) * PLANE + xr];
        }
        uint32_t hi, lo; cvt_hilo(v0, v1, hi, lo);
        uint32_t c16 = (uint32_t)kp >> 2;
        uint32_t off = (uint32_t)n * ROWB + ((c16 ^ ((uint32_t)n & 15)) << 4) + (((uint32_t)kp & 3) << 2);
        *(uint32_t*)(smem + BHI + off) = hi;
        *(uint32_t*)(smem + BLO + off) = lo;
    }
    __syncthreads();

    // ---- mma phase ----
    const int mt = warp >> 1;            // m-tile 0..3, m0 = 16*mt
    const int nh = warp & 1;             // n half
    const int m0 = 16 * mt;

    // A ldmatrix lane row/col-select
    const int lg = lane >> 3, l8 = lane & 7;
    const int arow = m0 + l8 + ((lg & 1) ? 8 : 0);
    const int asel = (lg >> 1);                     // k16 +0 / +1
    const uint32_t arow_off = (uint32_t)arow * ROWB;
    const uint32_t armask = (uint32_t)arow & 15;
    // B ldmatrix (lanes 0..15 meaningful; wrap for safety)
    const int bl = lane & 15;
    const int brow_rel = bl & 7;
    const int bsel = (bl >> 3);

    float C[4][4];
    #pragma unroll
    for (int t = 0; t < 4; t++)
        #pragma unroll
        for (int f = 0; f < 4; f++) C[t][f] = 0.f;

    #pragma unroll 1
    for (int kt = 0; kt < 8; kt++){
        uint32_t ak16 = (uint32_t)(2*kt + asel);
        uint32_t aoff = arow_off + ((ak16 ^ armask) << 4);
        uint32_t ah[4], al[4];
        ldsm_x4(ah, sb + AHI + aoff);
        ldsm_x4(al, sb + ALO + aoff);

        #pragma unroll
        for (int tn = 0; tn < 4; tn++){
            int p  = 2*mt + 4*nh + tn;        // n-tile index (n0 = 8p)
            int brow = 8*p + brow_rel;
            uint32_t bk16 = (uint32_t)(2*kt + bsel);
            uint32_t boff = (uint32_t)brow * ROWB + ((bk16 ^ ((uint32_t)brow & 15)) << 4);
            uint32_t bh2[2], bl2[2];
            ldsm_x2(bh2, sb + BHI + boff);
            ldsm_x2(bl2, sb + BLO + boff);
            mma16816(C[tn], ah, bh2);
            mma16816(C[tn], al, bh2);
            mma16816(C[tn], ah, bl2);
        }
    }
    __syncthreads();                      // before Obuf overlays A region

    // ---- band extract into Obuf[i][m] (stride 68 floats), scale 1/128 ----
    float* Ob = (float*)smem;             // 48*68*4 = 13056 B <= 16384 (AHI region)
    const int r  = lane >> 2;
    const int cb = 2 * (lane & 3);
    const float scale = 1.0f / 128.0f;
    #pragma unroll
    for (int tn = 0; tn < 4; tn++){
        int p = 2*mt + 4*nh + tn;
        #pragma unroll
        for (int f = 0; f < 4; f++){
            int row  = r + ((f >= 2) ? 8 : 0);
            int col  = cb + (f & 1);
            int mloc = m0 + row;
            int n    = 8*p + col;
            int i    = mloc + 48 - n;
            if (i >= 0 && i < MAXD)
                Ob[i * 68 + mloc] = C[tn][f] * scale;
        }
    }
    __syncthreads();

    // ---- coalesced store: 48 rows x 64 floats ----
    float* ob = out + (((size_t)b * MAXD) * HH + h) * WW + X0;
    #pragma unroll
    for (int q = tid; q < MAXD * 16; q += 256){
        int i = q >> 4, c4 = q & 15;
        float4 v = *(const float4*)(Ob + i * 68 + 4 * c4);
        *(float4*)(ob + (size_t)i * PLANE + 4 * c4) = v;
    }
}

extern "C" void kernel_launch(void* const* d_in, const int* in_sizes, int n_in,
                              void* d_out, int out_size)
{
    const float* L = (const float*)d_in[0];
    const float* R = (const float*)d_in[1];
    float* out = (float*)d_out;

    cudaFuncSetAttribute(costvol_mma_kernel,
                         cudaFuncAttributeMaxDynamicSharedMemorySize, SMEM_TOTAL);
    dim3 grid(BB * HH * 5);   // 3840 CTAs: (b, h, x-tile of 64)
    costvol_mma_kernel<<<grid, 256, SMEM_TOTAL>>>(L, R, out);
}

// round 7
// speedup vs baseline: 2.7050x; 1.6456x over previous
#include <cuda_runtime.h>
#include <cuda_bf16.h>
#include <cstdint>

// CostVolume: cost[b,i,h,x] = (1/128) sum_c L[b,c,h,x]*R[b,c,h,x-i], 0 for x<i.
// b=8 c=128 h=96 w=320, 48 disp, fp32.
// Banded GEMM on mma.sync.m16n8k16.bf16, fp32 via bf16 hi/lo split (3 passes).
// v7: K chunked in 4 slices of 32, register-prefetched converts overlapped
// with MMA of the previous slice; float4 loads; conflict-optimized swizzle.

#define BB 8
#define CH 128
#define HH 96
#define WW 320
#define MAXD 48
#define PLANE (HH*WW)

#define NT 112           // B rows (n window)
#define ROWB 256         // smem row bytes: full K=128 * 2B
#define AHI 0
#define ALO 16384
#define BHI 32768
#define BLO 61440
#define SMEM_TOTAL 90112

// swizzle col-perm: bijective on consecutive-8 rows (ldmatrix) AND stride-4 rows (STS)
__device__ __forceinline__ uint32_t gfun(uint32_t m){
    return ((((m>>2)&1)<<2) | ((((m>>1)^(m>>4))&1)<<1) | (((m^(m>>3))&1)));
}
__device__ __forceinline__ uint32_t smem_u32(const void* p){
    uint32_t a;
    asm("{ .reg .u64 t; cvta.to.shared.u64 t, %1; cvt.u32.u64 %0, t; }" : "=r"(a) : "l"(p));
    return a;
}
// hi = bf16-truncate pair (v0->low, v1->high), lo = rn(v - hi) pair
__device__ __forceinline__ void cvt_hilo(float v0, float v1, uint32_t& hi, uint32_t& lo){
    uint32_t u0 = __float_as_uint(v0), u1 = __float_as_uint(v1);
    uint32_t h; asm("prmt.b32 %0, %1, %2, 0x7632;" : "=r"(h) : "r"(u0), "r"(u1));
    float h0 = __uint_as_float(u0 & 0xFFFF0000u);
    float h1 = __uint_as_float(u1 & 0xFFFF0000u);
    float l0 = v0 - h0, l1 = v1 - h1;
    uint32_t l; asm("cvt.rn.bf16x2.f32 %0, %1, %2;" : "=r"(l) : "f"(l1), "f"(l0));
    hi = h; lo = l;
}
__device__ __forceinline__ void ldsm_x4(uint32_t* r, uint32_t addr){
    asm volatile("ldmatrix.sync.aligned.m8n8.x4.shared.b16 {%0,%1,%2,%3}, [%4];"
                 : "=r"(r[0]), "=r"(r[1]), "=r"(r[2]), "=r"(r[3]) : "r"(addr));
}
__device__ __forceinline__ void ldsm_x2(uint32_t* r, uint32_t addr){
    asm volatile("ldmatrix.sync.aligned.m8n8.x2.shared.b16 {%0,%1}, [%2];"
                 : "=r"(r[0]), "=r"(r[1]) : "r"(addr));
}
__device__ __forceinline__ void mma16816(float* c, const uint32_t* a, const uint32_t* b){
    asm volatile("mma.sync.aligned.m16n8k16.row.col.f32.bf16.bf16.f32 "
                 "{%0,%1,%2,%3}, {%4,%5,%6,%7}, {%8,%9}, {%0,%1,%2,%3};"
                 : "+f"(c[0]), "+f"(c[1]), "+f"(c[2]), "+f"(c[3])
                 : "r"(a[0]), "r"(a[1]), "r"(a[2]), "r"(a[3]), "r"(b[0]), "r"(b[1]));
}
__device__ __forceinline__ float4 zero4(){ return make_float4(0.f,0.f,0.f,0.f); }

__global__ __launch_bounds__(256, 2)
void costvol_v7_kernel(const float* __restrict__ L,
                       const float* __restrict__ R,
                       float* __restrict__ out)
{
    extern __shared__ char smem[];
    const uint32_t sb = smem_u32(smem);

    const int tid  = threadIdx.x;
    const int warp = tid >> 5;
    const int lane = tid & 31;

    const int xt = blockIdx.x % 5;
    const int bh = blockIdx.x / 5;
    const int h  = bh % HH;
    const int b  = bh / HH;
    const int X0 = 64 * xt;

    const float* Lbh = L + ((size_t)b * CH * HH + h) * WW;
    const float* Rbh = R + ((size_t)b * CH * HH + h) * WW;

    // ---- per-thread convert task constants ----
    const int kplA = tid >> 4;            // 0..15
    const int m4a  = tid & 15;            // 0..15
    const float* pLa = Lbh + X0 + 4 * m4a;
    uint32_t gA[4];
    #pragma unroll
    for (int e = 0; e < 4; e++) gA[e] = gfun((uint32_t)(4*m4a + e));

    const int tB0 = tid;                  // B task 0 (always active)
    const int kplB0 = tB0 / 28, n4b0 = tB0 - 28 * kplB0;
    const int tB1 = tid + 256;            // B task 1 (active if < 448)
    const bool act1 = (tB1 < 448);
    const int kplB1 = act1 ? tB1 / 28 : 0;
    const int n4b1  = act1 ? (tB1 - 28 * kplB1) : 0;
    const int xrB0 = X0 - 48 + 4 * n4b0;
    const int xrB1 = X0 - 48 + 4 * n4b1;
    uint32_t gB0[4], gB1[4];
    #pragma unroll
    for (int e = 0; e < 4; e++){
        gB0[e] = gfun((uint32_t)(4*n4b0 + e));
        gB1[e] = gfun((uint32_t)(4*n4b1 + e));
    }

    // ---- mma lane constants ----
    const int mt = warp >> 1, nh = warp & 1;
    const int m0 = 16 * mt;
    const int lg = lane >> 3, l8 = lane & 7;
    const int arow = m0 + l8 + ((lg & 1) ? 8 : 0);
    const int asel = lg >> 1;
    const uint32_t gArow = gfun((uint32_t)arow);
    const int bl = lane & 15;
    const int brow_rel = bl & 7;
    const int bsel = bl >> 3;
    int  browv[4]; uint32_t gBrow[4];
    #pragma unroll
    for (int tn = 0; tn < 4; tn++){
        int p = 2*mt + 4*nh + tn;
        browv[tn] = 8*p + brow_rel;
        gBrow[tn] = gfun((uint32_t)browv[tn]);
    }

    float C[4][4];
    #pragma unroll
    for (int t = 0; t < 4; t++)
        #pragma unroll
        for (int f = 0; f < 4; f++) C[t][f] = 0.f;

    // prefetch registers
    float4 a0, a1, b00, b01, b10, b11;

    auto prefetch = [&](int kc){
        int c0a = 2 * (kc * 16 + kplA);
        a0 = *(const float4*)(pLa + (size_t)c0a * PLANE);
        a1 = *(const float4*)(pLa + (size_t)(c0a + 1) * PLANE);
        int c0b = 2 * (kc * 16 + kplB0);
        if (xrB0 >= 0){
            b00 = *(const float4*)(Rbh + (size_t)c0b * PLANE + xrB0);
            b01 = *(const float4*)(Rbh + (size_t)(c0b + 1) * PLANE + xrB0);
        } else { b00 = zero4(); b01 = zero4(); }
        int c1b = 2 * (kc * 16 + kplB1);
        if (act1 && xrB1 >= 0){
            b10 = *(const float4*)(Rbh + (size_t)c1b * PLANE + xrB1);
            b11 = *(const float4*)(Rbh + (size_t)(c1b + 1) * PLANE + xrB1);
        } else { b10 = zero4(); b11 = zero4(); }
    };

    auto convert_sts = [&](int kc){
        // A slice
        {
            uint32_t kpg = (uint32_t)(kc * 16 + kplA);
            uint32_t c16 = kpg >> 2, w = kpg & 3;
            const float va[4] = {a0.x, a0.y, a0.z, a0.w};
            const float vb[4] = {a1.x, a1.y, a1.z, a1.w};
            #pragma unroll
            for (int e = 0; e < 4; e++){
                uint32_t hi, lo; cvt_hilo(va[e], vb[e], hi, lo);
                uint32_t m = (uint32_t)(4*m4a + e);
                uint32_t off = m * ROWB + ((c16 ^ gA[e]) << 4) + (w << 2);
                *(uint32_t*)(smem + AHI + off) = hi;
                *(uint32_t*)(smem + ALO + off) = lo;
            }
        }
        // B slice task 0
        {
            uint32_t kpg = (uint32_t)(kc * 16 + kplB0);
            uint32_t c16 = kpg >> 2, w = kpg & 3;
            const float va[4] = {b00.x, b00.y, b00.z, b00.w};
            const float vb[4] = {b01.x, b01.y, b01.z, b01.w};
            #pragma unroll
            for (int e = 0; e < 4; e++){
                uint32_t hi, lo; cvt_hilo(va[e], vb[e], hi, lo);
                uint32_t n = (uint32_t)(4*n4b0 + e);
                uint32_t off = n * ROWB + ((c16 ^ gB0[e]) << 4) + (w << 2);
                *(uint32_t*)(smem + BHI + off) = hi;
                *(uint32_t*)(smem + BLO + off) = lo;
            }
        }
        // B slice task 1
        if (act1){
            uint32_t kpg = (uint32_t)(kc * 16 + kplB1);
            uint32_t c16 = kpg >> 2, w = kpg & 3;
            const float va[4] = {b10.x, b10.y, b10.z, b10.w};
            const float vb[4] = {b11.x, b11.y, b11.z, b11.w};
            #pragma unroll
            for (int e = 0; e < 4; e++){
                uint32_t hi, lo; cvt_hilo(va[e], vb[e], hi, lo);
                uint32_t n = (uint32_t)(4*n4b1 + e);
                uint32_t off = n * ROWB + ((c16 ^ gB1[e]) << 4) + (w << 2);
                *(uint32_t*)(smem + BHI + off) = hi;
                *(uint32_t*)(smem + BLO + off) = lo;
            }
        }
    };

    // ---- pipelined main loop: convert(kc) | prefetch(kc+1) | bar | mma(kc) ----
    prefetch(0);
    #pragma unroll 1
    for (int kc = 0; kc < 4; kc++){
        convert_sts(kc);
        if (kc < 3) prefetch(kc + 1);
        __syncthreads();                 // slice kc visible to all warps

        #pragma unroll
        for (int ktl = 0; ktl < 2; ktl++){
            uint32_t colA = (uint32_t)(kc * 4 + 2 * ktl + asel);
            uint32_t aoff = (uint32_t)arow * ROWB + ((colA ^ gArow) << 4);
            uint32_t ah[4], al[4];
            ldsm_x4(ah, sb + AHI + aoff);
            ldsm_x4(al, sb + ALO + aoff);
            #pragma unroll
            for (int tn = 0; tn < 4; tn++){
                uint32_t colB = (uint32_t)(kc * 4 + 2 * ktl + bsel);
                uint32_t boff = (uint32_t)browv[tn] * ROWB + ((colB ^ gBrow[tn]) << 4);
                uint32_t bh2[2], bl2[2];
                ldsm_x2(bh2, sb + BHI + boff);
                ldsm_x2(bl2, sb + BLO + boff);
                mma16816(C[tn], ah, bh2);
                mma16816(C[tn], al, bh2);
                mma16816(C[tn], ah, bl2);
            }
        }
        // no 2nd barrier: next convert writes a disjoint k-slice
    }
    __syncthreads();                     // all mma done before Obuf overlays A

    // ---- band extract into Obuf[i][m] (stride 68 floats), scale 1/128 ----
    float* Ob = (float*)smem;            // 48*68*4 = 13056 B
    const int r  = lane >> 2;
    const int cb = 2 * (lane & 3);
    const float scale = 1.0f / 128.0f;
    #pragma unroll
    for (int tn = 0; tn < 4; tn++){
        int p = 2*mt + 4*nh + tn;
        #pragma unroll
        for (int f = 0; f < 4; f++){
            int row  = r + ((f >= 2) ? 8 : 0);
            int col  = cb + (f & 1);
            int mloc = m0 + row;
            int n    = 8*p + col;
            int i    = mloc + 48 - n;
            if (i >= 0 && i < MAXD)
                Ob[i * 68 + mloc] = C[tn][f] * scale;
        }
    }
    __syncthreads();

    // ---- coalesced store: 48 rows x 64 floats ----
    float* ob = out + (((size_t)b * MAXD) * HH + h) * WW + X0;
    #pragma unroll
    for (int q = tid; q < MAXD * 16; q += 256){
        int i = q >> 4, c4 = q & 15;
        float4 v = *(const float4*)(Ob + i * 68 + 4 * c4);
        *(float4*)(ob + (size_t)i * PLANE + 4 * c4) = v;
    }
}

extern "C" void kernel_launch(void* const* d_in, const int* in_sizes, int n_in,
                              void* d_out, int out_size)
{
    const float* L = (const float*)d_in[0];
    const float* R = (const float*)d_in[1];
    float* out = (float*)d_out;

    cudaFuncSetAttribute(costvol_v7_kernel,
                         cudaFuncAttributeMaxDynamicSharedMemorySize, SMEM_TOTAL);
    dim3 grid(BB * HH * 5);   // 3840 CTAs: (b, h, x-tile of 64)
    costvol_v7_kernel<<<grid, 256, SMEM_TOTAL>>>(L, R, out);
}

// round 8
// speedup vs baseline: 3.5992x; 1.3306x over previous
#include <cuda_runtime.h>
#include <cuda_fp16.h>
#include <cstdint>

// CostVolume: cost[b,i,h,x] = (1/128) sum_c L[b,c,h,x]*R[b,c,h,x-i], 0 for x<i.
// b=8 c=128 h=96 w=320, 48 disp, fp32.
// v8: single-pass fp16 mma.sync.m16n8k16 (fp32 accumulate). Error model
// (validated against R6's measured 1.33e-5 for the bf16 3-pass) predicts
// rel_err ~2-4e-4 < 1e-3. K pipelined in 4 slices of 32 channels, register
// prefetch overlapped with MMA; x4 ldmatrix for A and B (B over tn-pairs).

#define BB 8
#define CH 128
#define HH 96
#define WW 320
#define MAXD 48
#define PLANE (HH*WW)

#define NT 112           // B rows (n window)
#define ROWB 256         // smem row bytes: 128 k-values * 2B (64 pair-words)
#define AF 0             // A fp16 tile: 64*256 = 16384
#define BF 16384         // B fp16 tile: 112*256 = 28672
#define SMEM_TOTAL 45056

// col-perm swizzle: bijective on consecutive-8 rows (ldmatrix) and stride-4 rows (STS)
__device__ __forceinline__ uint32_t gfun(uint32_t m){
    return ((((m>>2)&1)<<2) | ((((m>>1)^(m>>4))&1)<<1) | (((m^(m>>3))&1)));
}
__device__ __forceinline__ uint32_t smem_u32(const void* p){
    uint32_t a;
    asm("{ .reg .u64 t; cvta.to.shared.u64 t, %1; cvt.u32.u64 %0, t; }" : "=r"(a) : "l"(p));
    return a;
}
// pack (v0 -> low half, v1 -> high half) as fp16x2
__device__ __forceinline__ uint32_t cvt_f16x2(float v0, float v1){
    uint32_t r;
    asm("cvt.rn.f16x2.f32 %0, %1, %2;" : "=r"(r) : "f"(v1), "f"(v0));
    return r;
}
__device__ __forceinline__ void ldsm_x4(uint32_t* r, uint32_t addr){
    asm volatile("ldmatrix.sync.aligned.m8n8.x4.shared.b16 {%0,%1,%2,%3}, [%4];"
                 : "=r"(r[0]), "=r"(r[1]), "=r"(r[2]), "=r"(r[3]) : "r"(addr));
}
__device__ __forceinline__ void mma16816(float* c, const uint32_t* a, const uint32_t* b){
    asm volatile("mma.sync.aligned.m16n8k16.row.col.f32.f16.f16.f32 "
                 "{%0,%1,%2,%3}, {%4,%5,%6,%7}, {%8,%9}, {%0,%1,%2,%3};"
                 : "+f"(c[0]), "+f"(c[1]), "+f"(c[2]), "+f"(c[3])
                 : "r"(a[0]), "r"(a[1]), "r"(a[2]), "r"(a[3]), "r"(b[0]), "r"(b[1]));
}
__device__ __forceinline__ float4 zero4(){ return make_float4(0.f,0.f,0.f,0.f); }

__global__ __launch_bounds__(256, 3)
void costvol_v8_kernel(const float* __restrict__ L,
                       const float* __restrict__ R,
                       float* __restrict__ out)
{
    extern __shared__ char smem[];
    const uint32_t sb = smem_u32(smem);

    const int tid  = threadIdx.x;
    const int warp = tid >> 5;
    const int lane = tid & 31;

    const int xt = blockIdx.x % 5;
    const int bh = blockIdx.x / 5;
    const int h  = bh % HH;
    const int b  = bh / HH;
    const int X0 = 64 * xt;

    const float* Lbh = L + ((size_t)b * CH * HH + h) * WW;
    const float* Rbh = R + ((size_t)b * CH * HH + h) * WW;

    // ---- convert task constants ----
    const int kplA = tid >> 4;            // 0..15 (k-pair within slice)
    const int m4a  = tid & 15;
    const float* pLa = Lbh + X0 + 4 * m4a;
    uint32_t gA[4];
    #pragma unroll
    for (int e = 0; e < 4; e++) gA[e] = gfun((uint32_t)(4*m4a + e));

    const int tB0 = tid;
    const int kplB0 = tB0 / 28, n4b0 = tB0 - 28 * kplB0;
    const int tB1 = tid + 256;
    const bool act1 = (tB1 < 448);
    const int kplB1 = act1 ? tB1 / 28 : 0;
    const int n4b1  = act1 ? (tB1 - 28 * kplB1) : 0;
    const int xrB0 = X0 - 48 + 4 * n4b0;
    const int xrB1 = X0 - 48 + 4 * n4b1;
    uint32_t gB0[4], gB1[4];
    #pragma unroll
    for (int e = 0; e < 4; e++){
        gB0[e] = gfun((uint32_t)(4*n4b0 + e));
        gB1[e] = gfun((uint32_t)(4*n4b1 + e));
    }

    // ---- mma lane constants ----
    const int mt = warp >> 1, nh = warp & 1;
    const int m0 = 16 * mt;
    const int lg = lane >> 3, l8 = lane & 7;
    const int arow = m0 + l8 + ((lg & 1) ? 8 : 0);
    const int asel = lg >> 1;
    const uint32_t gArow = gfun((uint32_t)arow);
    // B x4 over tn-pairs: lane -> (pair offset, row, k16 half)
    const int colselB = (lane >> 3) & 1;
    int browv[2]; uint32_t gBrow[2];
    #pragma unroll
    for (int j = 0; j < 2; j++){
        int p = 2*mt + 4*nh + 2*j + ((lane >> 4) & 1);
        browv[j] = 8*p + (lane & 7);
        gBrow[j] = gfun((uint32_t)browv[j]);
    }

    float C[4][4];
    #pragma unroll
    for (int t = 0; t < 4; t++)
        #pragma unroll
        for (int f = 0; f < 4; f++) C[t][f] = 0.f;

    float4 a0, a1, b00, b01, b10, b11;

    auto prefetch = [&](int kc){
        int c0a = 2 * (kc * 16 + kplA);
        a0 = *(const float4*)(pLa + (size_t)c0a * PLANE);
        a1 = *(const float4*)(pLa + (size_t)(c0a + 1) * PLANE);
        int c0b = 2 * (kc * 16 + kplB0);
        if (xrB0 >= 0){
            b00 = *(const float4*)(Rbh + (size_t)c0b * PLANE + xrB0);
            b01 = *(const float4*)(Rbh + (size_t)(c0b + 1) * PLANE + xrB0);
        } else { b00 = zero4(); b01 = zero4(); }
        int c1b = 2 * (kc * 16 + kplB1);
        if (act1 && xrB1 >= 0){
            b10 = *(const float4*)(Rbh + (size_t)c1b * PLANE + xrB1);
            b11 = *(const float4*)(Rbh + (size_t)(c1b + 1) * PLANE + xrB1);
        } else { b10 = zero4(); b11 = zero4(); }
    };

    auto convert_sts = [&](int kc){
        {   // A slice
            uint32_t kpg = (uint32_t)(kc * 16 + kplA);
            uint32_t c16 = kpg >> 2, w = kpg & 3;
            const float va[4] = {a0.x, a0.y, a0.z, a0.w};
            const float vb[4] = {a1.x, a1.y, a1.z, a1.w};
            #pragma unroll
            for (int e = 0; e < 4; e++){
                uint32_t m = (uint32_t)(4*m4a + e);
                uint32_t off = m * ROWB + ((c16 ^ gA[e]) << 4) + (w << 2);
                *(uint32_t*)(smem + AF + off) = cvt_f16x2(va[e], vb[e]);
            }
        }
        {   // B slice task 0
            uint32_t kpg = (uint32_t)(kc * 16 + kplB0);
            uint32_t c16 = kpg >> 2, w = kpg & 3;
            const float va[4] = {b00.x, b00.y, b00.z, b00.w};
            const float vb[4] = {b01.x, b01.y, b01.z, b01.w};
            #pragma unroll
            for (int e = 0; e < 4; e++){
                uint32_t n = (uint32_t)(4*n4b0 + e);
                uint32_t off = n * ROWB + ((c16 ^ gB0[e]) << 4) + (w << 2);
                *(uint32_t*)(smem + BF + off) = cvt_f16x2(va[e], vb[e]);
            }
        }
        if (act1){  // B slice task 1
            uint32_t kpg = (uint32_t)(kc * 16 + kplB1);
            uint32_t c16 = kpg >> 2, w = kpg & 3;
            const float va[4] = {b10.x, b10.y, b10.z, b10.w};
            const float vb[4] = {b11.x, b11.y, b11.z, b11.w};
            #pragma unroll
            for (int e = 0; e < 4; e++){
                uint32_t n = (uint32_t)(4*n4b1 + e);
                uint32_t off = n * ROWB + ((c16 ^ gB1[e]) << 4) + (w << 2);
                *(uint32_t*)(smem + BF + off) = cvt_f16x2(va[e], vb[e]);
            }
        }
    };

    // ---- pipelined main loop: convert(kc) | prefetch(kc+1) | bar | mma(kc) ----
    prefetch(0);
    #pragma unroll 1
    for (int kc = 0; kc < 4; kc++){
        convert_sts(kc);
        if (kc < 3) prefetch(kc + 1);
        __syncthreads();                 // slice kc visible

        #pragma unroll
        for (int ktl = 0; ktl < 2; ktl++){
            uint32_t colA = (uint32_t)(kc * 4 + 2 * ktl + asel);
            uint32_t aoff = (uint32_t)arow * ROWB + ((colA ^ gArow) << 4);
            uint32_t af[4];
            ldsm_x4(af, sb + AF + aoff);
            #pragma unroll
            for (int j = 0; j < 2; j++){
                uint32_t colB = (uint32_t)(kc * 4 + 2 * ktl + colselB);
                uint32_t boff = (uint32_t)browv[j] * ROWB + ((colB ^ gBrow[j]) << 4);
                uint32_t bf[4];
                ldsm_x4(bf, sb + BF + boff);
                mma16816(C[2*j],     af, bf);       // tn = 2j
                mma16816(C[2*j + 1], af, bf + 2);   // tn = 2j+1
            }
        }
        // no 2nd barrier: next convert writes a disjoint k-slice
    }
    __syncthreads();                     // all mma done before Obuf overlays A

    // ---- band extract into Obuf[i][m] (stride 68), scale 1/128 ----
    float* Ob = (float*)smem;            // 48*68*4 = 13056 B
    const int r  = lane >> 2;
    const int cb = 2 * (lane & 3);
    const float scale = 1.0f / 128.0f;
    #pragma unroll
    for (int tn = 0; tn < 4; tn++){
        int p = 2*mt + 4*nh + tn;
        #pragma unroll
        for (int f = 0; f < 4; f++){
            int row  = r + ((f >= 2) ? 8 : 0);
            int col  = cb + (f & 1);
            int mloc = m0 + row;
            int n    = 8*p + col;
            int i    = mloc + 48 - n;
            if (i >= 0 && i < MAXD)
                Ob[i * 68 + mloc] = C[tn][f] * scale;
        }
    }
    __syncthreads();

    // ---- coalesced store: 48 rows x 64 floats ----
    float* ob = out + (((size_t)b * MAXD) * HH + h) * WW + X0;
    #pragma unroll
    for (int q = tid; q < MAXD * 16; q += 256){
        int i = q >> 4, c4 = q & 15;
        float4 v = *(const float4*)(Ob + i * 68 + 4 * c4);
        *(float4*)(ob + (size_t)i * PLANE + 4 * c4) = v;
    }
}

extern "C" void kernel_launch(void* const* d_in, const int* in_sizes, int n_in,
                              void* d_out, int out_size)
{
    const float* L = (const float*)d_in[0];
    const float* R = (const float*)d_in[1];
    float* out = (float*)d_out;

    cudaFuncSetAttribute(costvol_v8_kernel,
                         cudaFuncAttributeMaxDynamicSharedMemorySize, SMEM_TOTAL);
    dim3 grid(BB * HH * 5);   // 3840 CTAs: (b, h, x-tile of 64)
    costvol_v8_kernel<<<grid, 256, SMEM_TOTAL>>>(L, R, out);
}